// round 5
// baseline (speedup 1.0000x reference)
#include <cuda_runtime.h>
#include <cuda_bf16.h>

// Problem constants
#define Bn 8
#define Tn 1024
#define Fn 512
#define Dn 64
#define ROWS (Bn*Tn)       // 8192
#define TC 32              // scan chunk length
#define NCH 32             // scan chunks (Tn/TC)

// GEMM tiling
#define MBLK 64            // rows per block
#define NTOT 192           // output cols (K|Q|V)
#define KCH  128           // K chunk in bf16 elems
#define NKC  (Fn/KCH)      // 4 chunks
#define LDA  136           // smem tile stride in bf16 (128 + 8 pad)
#define LDAB (LDA*2)       // 272 bytes
#define OUTS 204           // epilogue fp32 tile stride

// smem byte offsets
#define SM_AHI   0
#define SM_ALO   (SM_AHI + MBLK*LDAB)     // 17408
#define SM_BHI   (SM_ALO + MBLK*LDAB)     // 34816
#define SM_BLO   (SM_BHI + NTOT*LDAB)     // 87040
#define SM_STATS (SM_BLO + NTOT*LDAB)     // 139264
#define SM_TOT   (SM_STATS + MBLK*2*4)    // 139776

// Scratch
__device__ float g_K[ROWS*Dn];
__device__ float g_Q[ROWS*Dn];
__device__ float g_V[ROWS*Dn];
__device__ float g_S[Bn*NCH*Dn*Dn];
__device__ unsigned short g_Whi[NTOT*Fn];   // bf16 [n][k]
__device__ unsigned short g_Wlo[NTOT*Fn];

__device__ __forceinline__ unsigned smem_u32(const void* p){
    unsigned a;
    asm("{ .reg .u64 t; cvta.to.shared.u64 t, %1; cvt.u32.u64 %0, t; }" : "=r"(a) : "l"(p));
    return a;
}

#define LDSM4(r, addr) \
    asm volatile("ldmatrix.sync.aligned.m8n8.x4.shared.b16 {%0,%1,%2,%3}, [%4];" \
        : "=r"((r)[0]), "=r"((r)[1]), "=r"((r)[2]), "=r"((r)[3]) : "r"(addr))

#define MMA_BF16(d, a, b0, b1) \
    asm volatile("mma.sync.aligned.m16n8k16.row.col.f32.bf16.bf16.f32 " \
        "{%0,%1,%2,%3}, {%4,%5,%6,%7}, {%8,%9}, {%0,%1,%2,%3};" \
        : "+f"((d)[0]), "+f"((d)[1]), "+f"((d)[2]), "+f"((d)[3]) \
        : "r"((a)[0]), "r"((a)[1]), "r"((a)[2]), "r"((a)[3]), "r"(b0), "r"(b1))

__device__ __forceinline__ unsigned pack_bf2(float v0, float v1, unsigned short* lo0, unsigned short* lo1){
    __nv_bfloat16 h0 = __float2bfloat16(v0);
    __nv_bfloat16 h1 = __float2bfloat16(v1);
    *lo0 = __bfloat16_as_ushort(__float2bfloat16(v0 - __bfloat162float(h0)));
    *lo1 = __bfloat16_as_ushort(__float2bfloat16(v1 - __bfloat162float(h1)));
    return (unsigned)__bfloat16_as_ushort(h0) | ((unsigned)__bfloat16_as_ushort(h1) << 16);
}

// ---------------------------------------------------------------------------
// W-prep: transpose + split W into bf16 hi/lo [192][512]
// ---------------------------------------------------------------------------
__global__ void __launch_bounds__(256) wprep_kernel(
    const float* __restrict__ Wk, const float* __restrict__ Wq,
    const float* __restrict__ Wv)
{
    const int n = blockIdx.x;
    const int m = n >> 6, j = n & 63;
    const float* W = (m == 0) ? Wk : ((m == 1) ? Wq : Wv);
    const int k0 = threadIdx.x * 2;
    float v0 = __ldg(W + (size_t)k0*Dn + j);
    float v1 = __ldg(W + (size_t)(k0+1)*Dn + j);
    unsigned short l0, l1;
    unsigned hi = pack_bf2(v0, v1, &l0, &l1);
    unsigned lo = (unsigned)l0 | ((unsigned)l1 << 16);
    reinterpret_cast<unsigned*>(g_Whi)[n*(Fn/2) + threadIdx.x] = hi;
    reinterpret_cast<unsigned*>(g_Wlo)[n*(Fn/2) + threadIdx.x] = lo;
}

// ---------------------------------------------------------------------------
// Kernel A: LN + split-bf16 mma.sync GEMM + relu/sum-norm epilogue
// grid 128, block 256 (8 warps: 2(M) x 4(N); warp tile 32x48)
// ---------------------------------------------------------------------------
__global__ void __launch_bounds__(256) ln_mma_kernel(
    const float* __restrict__ x,
    const float* __restrict__ gamma, const float* __restrict__ beta)
{
    extern __shared__ char smem[];
    const int tid = threadIdx.x, w = tid >> 5, l = tid & 31;
    const int row0 = blockIdx.x * MBLK;
    float* stats = reinterpret_cast<float*>(smem + SM_STATS);

    // ---- LN stats: warp w -> rows w*8 .. w*8+7
    for (int r8 = 0; r8 < 8; r8++) {
        const int r = w*8 + r8;
        const float4* xr = reinterpret_cast<const float4*>(x + (size_t)(row0 + r) * Fn);
        float s = 0.f, ss = 0.f;
#pragma unroll
        for (int q = 0; q < 4; q++) {
            float4 v = xr[q*32 + l];
            s  += v.x + v.y + v.z + v.w;
            ss += v.x*v.x + v.y*v.y + v.z*v.z + v.w*v.w;
        }
#pragma unroll
        for (int o = 16; o; o >>= 1) {
            s  += __shfl_xor_sync(0xffffffffu, s,  o);
            ss += __shfl_xor_sync(0xffffffffu, ss, o);
        }
        if (l == 0) {
            float mu = s * (1.f/512.f);
            float var = ss * (1.f/512.f) - mu*mu;
            stats[r*2]   = mu;
            stats[r*2+1] = rsqrtf(var + 1e-5f);
        }
    }
    __syncthreads();

    // ---- per-lane ldmatrix base addresses
    const unsigned sbase = smem_u32(smem);
    const int wm = w >> 2, wn = w & 3;
    unsigned a_off[2], b_off[3];
#pragma unroll
    for (int mt = 0; mt < 2; mt++)
        a_off[mt] = sbase + SM_AHI + (unsigned)(wm*32 + mt*16 + (l & 15))*LDAB + ((l >> 4) << 4);
#pragma unroll
    for (int p = 0; p < 3; p++) {
        int n = wn*48 + p*16 + ((l >> 4) << 3) + (l & 7);
        b_off[p] = sbase + SM_BHI + (unsigned)n*LDAB + (((l >> 3) & 1) << 4);
    }
    const unsigned ALO_D = SM_ALO - SM_AHI;
    const unsigned BLO_D = SM_BLO - SM_BHI;

    float acc[2][6][4];
#pragma unroll
    for (int mt = 0; mt < 2; mt++)
#pragma unroll
        for (int nt = 0; nt < 6; nt++)
#pragma unroll
            for (int e = 0; e < 4; e++) acc[mt][nt][e] = 0.f;

    // ---- K chunks
    for (int c = 0; c < NKC; c++) {
        __syncthreads();   // previous chunk's ldmatrix reads complete (sync ops)

        // stage A: 4 threads per row, 32 k each
        {
            const int r  = tid >> 2;
            const int k0 = (tid & 3) * 32;
            const float mu = stats[r*2], rstd = stats[r*2+1];
            const float* xp = x + (size_t)(row0 + r)*Fn + c*KCH + k0;
            const float* gp = gamma + c*KCH + k0;
            const float* bp = beta  + c*KCH + k0;
            char* ah = smem + SM_AHI + r*LDAB + k0*2;
            char* al = smem + SM_ALO + r*LDAB + k0*2;
#pragma unroll
            for (int q = 0; q < 4; q++) {
                float4 v0 = __ldg(reinterpret_cast<const float4*>(xp + q*8));
                float4 v1 = __ldg(reinterpret_cast<const float4*>(xp + q*8 + 4));
                float4 g0 = __ldg(reinterpret_cast<const float4*>(gp + q*8));
                float4 g1 = __ldg(reinterpret_cast<const float4*>(gp + q*8 + 4));
                float4 b0 = __ldg(reinterpret_cast<const float4*>(bp + q*8));
                float4 b1 = __ldg(reinterpret_cast<const float4*>(bp + q*8 + 4));
                float vv[8] = {v0.x,v0.y,v0.z,v0.w,v1.x,v1.y,v1.z,v1.w};
                float gg[8] = {g0.x,g0.y,g0.z,g0.w,g1.x,g1.y,g1.z,g1.w};
                float bb[8] = {b0.x,b0.y,b0.z,b0.w,b1.x,b1.y,b1.z,b1.w};
                unsigned hi[4], lo[4];
#pragma unroll
                for (int e = 0; e < 8; e++) vv[e] = (vv[e] - mu)*rstd*gg[e] + bb[e];
#pragma unroll
                for (int e = 0; e < 4; e++) {
                    unsigned short s0, s1;
                    hi[e] = pack_bf2(vv[2*e], vv[2*e+1], &s0, &s1);
                    lo[e] = (unsigned)s0 | ((unsigned)s1 << 16);
                }
                *reinterpret_cast<uint4*>(ah + q*16) = make_uint4(hi[0],hi[1],hi[2],hi[3]);
                *reinterpret_cast<uint4*>(al + q*16) = make_uint4(lo[0],lo[1],lo[2],lo[3]);
            }
        }

        // stage B: copy bf16 W chunk (already split). 256 bytes/row = 16 uint4.
        for (int idx = tid; idx < NTOT*16; idx += 256) {
            const int n = idx >> 4, q = idx & 15;
            const uint4* sh = reinterpret_cast<const uint4*>(g_Whi + (size_t)n*Fn + c*KCH) + q;
            const uint4* sl = reinterpret_cast<const uint4*>(g_Wlo + (size_t)n*Fn + c*KCH) + q;
            *reinterpret_cast<uint4*>(smem + SM_BHI + n*LDAB + q*16) = *sh;
            *reinterpret_cast<uint4*>(smem + SM_BLO + n*LDAB + q*16) = *sl;
        }
        __syncthreads();

        // 8 k-steps of 16
#pragma unroll
        for (int ks = 0; ks < 8; ks++) {
            const unsigned koff = ks*32;
            unsigned ahi[2][4], alo[2][4], bhi[3][4], blo[3][4];
#pragma unroll
            for (int mt = 0; mt < 2; mt++) {
                LDSM4(ahi[mt], a_off[mt] + koff);
                LDSM4(alo[mt], a_off[mt] + ALO_D + koff);
            }
#pragma unroll
            for (int p = 0; p < 3; p++) {
                LDSM4(bhi[p], b_off[p] + koff);
                LDSM4(blo[p], b_off[p] + BLO_D + koff);
            }
#pragma unroll
            for (int mt = 0; mt < 2; mt++)
#pragma unroll
                for (int nt = 0; nt < 6; nt++) {
                    const int p = nt >> 1, h = (nt & 1) * 2;
                    MMA_BF16(acc[mt][nt], ahi[mt], bhi[p][h], bhi[p][h+1]);
                    MMA_BF16(acc[mt][nt], ahi[mt], blo[p][h], blo[p][h+1]);
                    MMA_BF16(acc[mt][nt], alo[mt], bhi[p][h], bhi[p][h+1]);
                }
        }
    }

    // ---- epilogue: stage fp32 tile, normalize, store
    __syncthreads();
    float* outt = reinterpret_cast<float*>(smem);   // [64][OUTS] overlay
#pragma unroll
    for (int mt = 0; mt < 2; mt++)
#pragma unroll
        for (int nt = 0; nt < 6; nt++) {
            const int r   = wm*32 + mt*16 + (l >> 2);
            const int col = wn*48 + nt*8 + (l & 3)*2;
            *reinterpret_cast<float2*>(&outt[r*OUTS + col])     = make_float2(acc[mt][nt][0], acc[mt][nt][1]);
            *reinterpret_cast<float2*>(&outt[(r+8)*OUTS + col]) = make_float2(acc[mt][nt][2], acc[mt][nt][3]);
        }
    __syncthreads();

    for (int r8 = 0; r8 < 8; r8++) {
        const int r = w*8 + r8;
        const int grow = row0 + r;
        // K
        float k0v = fmaxf(outt[r*OUTS + l], 0.f);
        float k1v = fmaxf(outt[r*OUTS + 32 + l], 0.f);
        float s = k0v + k1v;
#pragma unroll
        for (int o = 16; o; o >>= 1) s += __shfl_xor_sync(0xffffffffu, s, o);
        float rs = 1.f / (1e-5f + s);
        g_K[(size_t)grow*Dn + l]      = k0v * rs;
        g_K[(size_t)grow*Dn + 32 + l] = k1v * rs;
        // Q
        float q0v = fmaxf(outt[r*OUTS + 64 + l], 0.f);
        float q1v = fmaxf(outt[r*OUTS + 96 + l], 0.f);
        s = q0v + q1v;
#pragma unroll
        for (int o = 16; o; o >>= 1) s += __shfl_xor_sync(0xffffffffu, s, o);
        rs = 1.f / (1e-5f + s);
        g_Q[(size_t)grow*Dn + l]      = q0v * rs;
        g_Q[(size_t)grow*Dn + 32 + l] = q1v * rs;
        // V
        g_V[(size_t)grow*Dn + l]      = outt[r*OUTS + 128 + l];
        g_V[(size_t)grow*Dn + 32 + l] = outt[r*OUTS + 160 + l];
    }
}

// ---------------------------------------------------------------------------
// Kernel B: per-(batch,chunk) outer-product sums
// ---------------------------------------------------------------------------
__global__ void __launch_bounds__(256) chunk_sum_kernel()
{
    __shared__ float Kc[TC*Dn], Vc[TC*Dn];
    const int c = blockIdx.x, b = blockIdx.y;
    const int base = (b*Tn + c*TC) * Dn;
    {
        const float4* Ks = reinterpret_cast<const float4*>(g_K + base);
        const float4* Vs = reinterpret_cast<const float4*>(g_V + base);
        float4* K4 = reinterpret_cast<float4*>(Kc);
        float4* V4 = reinterpret_cast<float4*>(Vc);
        for (int i = threadIdx.x; i < TC*Dn/4; i += 256) { K4[i] = Ks[i]; V4[i] = Vs[i]; }
    }
    __syncthreads();

    const int jg = threadIdx.x & 15, ig = threadIdx.x >> 4;
    float acc[4][4] = {};
#pragma unroll 4
    for (int t = 0; t < TC; t++) {
        float4 k4 = *reinterpret_cast<const float4*>(Kc + t*Dn + jg*4);
        float4 v4 = *reinterpret_cast<const float4*>(Vc + t*Dn + ig*4);
        float kk[4] = {k4.x, k4.y, k4.z, k4.w};
        float vv[4] = {v4.x, v4.y, v4.z, v4.w};
#pragma unroll
        for (int i = 0; i < 4; i++)
#pragma unroll
            for (int j = 0; j < 4; j++) acc[i][j] += vv[i]*kk[j];
    }
    float* S = g_S + (size_t)(b*NCH + c) * (Dn*Dn);
#pragma unroll
    for (int i = 0; i < 4; i++)
        *reinterpret_cast<float4*>(S + (ig*4 + i)*Dn + jg*4) =
            make_float4(acc[i][0], acc[i][1], acc[i][2], acc[i][3]);
}

// ---------------------------------------------------------------------------
// Kernel D: scan
// ---------------------------------------------------------------------------
__global__ void __launch_bounds__(256) scan_kernel(
    const float* __restrict__ state, float* __restrict__ out)
{
    __shared__ float Kc[TC*Dn], Qc[TC*Dn], Vc[TC*Dn];
    __shared__ float ypart[2][16][Dn];

    const int c = blockIdx.x, b = blockIdx.y;
    const int jg = threadIdx.x & 15, ig = threadIdx.x >> 4;

    float acc[4][4];
    {
        const float* st = state + (size_t)b * (Dn*Dn);
#pragma unroll
        for (int i = 0; i < 4; i++) {
            float4 s4 = __ldg(reinterpret_cast<const float4*>(st + (ig*4 + i)*Dn + jg*4));
            acc[i][0] = s4.x; acc[i][1] = s4.y; acc[i][2] = s4.z; acc[i][3] = s4.w;
        }
    }
    for (int cp = 0; cp < c; cp++) {
        const float* S = g_S + (size_t)(b*NCH + cp) * (Dn*Dn);
#pragma unroll
        for (int i = 0; i < 4; i++) {
            float4 s4 = __ldg(reinterpret_cast<const float4*>(S + (ig*4 + i)*Dn + jg*4));
            acc[i][0] += s4.x; acc[i][1] += s4.y; acc[i][2] += s4.z; acc[i][3] += s4.w;
        }
    }
    {
        const int base = (b*Tn + c*TC) * Dn;
        const float4* Ks = reinterpret_cast<const float4*>(g_K + base);
        const float4* Qs = reinterpret_cast<const float4*>(g_Q + base);
        const float4* Vs = reinterpret_cast<const float4*>(g_V + base);
        float4* K4 = reinterpret_cast<float4*>(Kc);
        float4* Q4 = reinterpret_cast<float4*>(Qc);
        float4* V4 = reinterpret_cast<float4*>(Vc);
        for (int i = threadIdx.x; i < TC*Dn/4; i += 256) { K4[i] = Ks[i]; Q4[i] = Qs[i]; V4[i] = Vs[i]; }
    }
    __syncthreads();

    float* yout = out;
    float* sout = out + (size_t)ROWS * Dn;

    for (int t = 0; t < TC; t++) {
        const int rglob = b*Tn + c*TC + t;
        float4 k4 = *reinterpret_cast<const float4*>(Kc + t*Dn + jg*4);
        float4 q4 = *reinterpret_cast<const float4*>(Qc + t*Dn + ig*4);
        float4 v4 = *reinterpret_cast<const float4*>(Vc + t*Dn + ig*4);
        float kk[4] = {k4.x, k4.y, k4.z, k4.w};
        float qq[4] = {q4.x, q4.y, q4.z, q4.w};
        float vv[4] = {v4.x, v4.y, v4.z, v4.w};

        float yp[4] = {0.f, 0.f, 0.f, 0.f};
#pragma unroll
        for (int i = 0; i < 4; i++) {
#pragma unroll
            for (int j = 0; j < 4; j++) {
                acc[i][j] += vv[i]*kk[j];
                yp[j]     += acc[i][j]*qq[i];
            }
            *reinterpret_cast<float4*>(sout + (size_t)rglob*(Dn*Dn) + (ig*4 + i)*Dn + jg*4) =
                make_float4(acc[i][0], acc[i][1], acc[i][2], acc[i][3]);
        }

        const int pb = t & 1;
        *reinterpret_cast<float4*>(&ypart[pb][ig][jg*4]) = make_float4(yp[0], yp[1], yp[2], yp[3]);
        __syncthreads();
        if (threadIdx.x < Dn) {
            float s = 0.f;
#pragma unroll
            for (int g = 0; g < 16; g++) s += ypart[pb][g][threadIdx.x];
            yout[(size_t)rglob*Dn + threadIdx.x] = s;
        }
    }
}

// ---------------------------------------------------------------------------
extern "C" void kernel_launch(void* const* d_in, const int* in_sizes, int n_in,
                              void* d_out, int out_size)
{
    const float* x     = (const float*)d_in[0];
    const float* state = (const float*)d_in[1];
    const float* Wk    = (const float*)d_in[2];
    const float* Wq    = (const float*)d_in[3];
    const float* Wv    = (const float*)d_in[4];
    const float* gamma = (const float*)d_in[5];
    const float* beta  = (const float*)d_in[6];
    float* out = (float*)d_out;

    cudaFuncSetAttribute(ln_mma_kernel, cudaFuncAttributeMaxDynamicSharedMemorySize, SM_TOT);

    wprep_kernel<<<NTOT, 256>>>(Wk, Wq, Wv);
    ln_mma_kernel<<<ROWS/MBLK, 256, SM_TOT>>>(x, gamma, beta);
    chunk_sum_kernel<<<dim3(NCH, Bn), 256>>>();
    scan_kernel<<<dim3(NCH, Bn), 256>>>(state, out);
}

// round 6
// speedup vs baseline: 1.1936x; 1.1936x over previous
#include <cuda_runtime.h>
#include <cuda_bf16.h>

// Problem constants
#define Bn 8
#define Tn 1024
#define Fn 512
#define Dn 64
#define ROWS (Bn*Tn)       // 8192
#define TC 32              // scan chunk length
#define NCH 32             // scan chunks (Tn/TC)

// GEMM tiling
#define MBLK 64            // rows per block
#define NTOT 192           // total output cols (K|Q|V)
#define KCH  128           // K chunk in bf16 elems
#define NKC  (Fn/KCH)      // 4 chunks
#define LDA  136           // smem tile stride in bf16 (128 + 8 pad)
#define LDAB (LDA*2)       // 272 bytes
#define OUTS 68            // epilogue fp32 tile stride (64 + 4)

// GEMM smem byte offsets (dynamic)
#define SM_AHI   0
#define SM_ALO   (SM_AHI + MBLK*LDAB)     // 17408
#define SM_BHI   (SM_ALO + MBLK*LDAB)     // 34816
#define SM_BLO   (SM_BHI + Dn*LDAB)       // 52224
#define SM_TOT   (SM_BLO + Dn*LDAB)       // 69632

// Scan smem (floats)
#define SC_KC   0                          // [32][32]
#define SC_QC   (SC_KC + TC*32)            // [32][64]
#define SC_VC   (SC_QC + TC*Dn)            // [32][64]
#define SC_YP   (SC_VC + TC*Dn)            // float2[32][8][16] = 8192 floats
#define SC_TOTF (SC_YP + TC*8*16*2)        // 13312 floats = 53248 B

// Scratch
__device__ float g_K[ROWS*Dn];
__device__ float g_Q[ROWS*Dn];
__device__ float g_V[ROWS*Dn];
__device__ float g_S[Bn*NCH*Dn*Dn];
__device__ float g_P[Bn*NCH*Dn*Dn];         // chunk-prefix states
__device__ unsigned short g_Whi[NTOT*Fn];   // bf16 [n][k]
__device__ unsigned short g_Wlo[NTOT*Fn];
__device__ unsigned short g_Xhi[ROWS*Fn];   // LN'd x, bf16 hi
__device__ unsigned short g_Xlo[ROWS*Fn];   // bf16 lo

__device__ __forceinline__ unsigned smem_u32(const void* p){
    unsigned a;
    asm("{ .reg .u64 t; cvta.to.shared.u64 t, %1; cvt.u32.u64 %0, t; }" : "=r"(a) : "l"(p));
    return a;
}

#define LDSM4(r, addr) \
    asm volatile("ldmatrix.sync.aligned.m8n8.x4.shared.b16 {%0,%1,%2,%3}, [%4];" \
        : "=r"((r)[0]), "=r"((r)[1]), "=r"((r)[2]), "=r"((r)[3]) : "r"(addr))

#define MMA_BF16(d, a, b0, b1) \
    asm volatile("mma.sync.aligned.m16n8k16.row.col.f32.bf16.bf16.f32 " \
        "{%0,%1,%2,%3}, {%4,%5,%6,%7}, {%8,%9}, {%0,%1,%2,%3};" \
        : "+f"((d)[0]), "+f"((d)[1]), "+f"((d)[2]), "+f"((d)[3]) \
        : "r"((a)[0]), "r"((a)[1]), "r"((a)[2]), "r"((a)[3]), "r"(b0), "r"(b1))

__device__ __forceinline__ unsigned pack_bf2(float v0, float v1, unsigned short* lo0, unsigned short* lo1){
    __nv_bfloat16 h0 = __float2bfloat16(v0);
    __nv_bfloat16 h1 = __float2bfloat16(v1);
    *lo0 = __bfloat16_as_ushort(__float2bfloat16(v0 - __bfloat162float(h0)));
    *lo1 = __bfloat16_as_ushort(__float2bfloat16(v1 - __bfloat162float(h1)));
    return (unsigned)__bfloat16_as_ushort(h0) | ((unsigned)__bfloat16_as_ushort(h1) << 16);
}

// ---------------------------------------------------------------------------
// W-prep: transpose + split W into bf16 hi/lo [192][512]
// ---------------------------------------------------------------------------
__global__ void __launch_bounds__(256) wprep_kernel(
    const float* __restrict__ Wk, const float* __restrict__ Wq,
    const float* __restrict__ Wv)
{
    const int n = blockIdx.x;
    const int m = n >> 6, j = n & 63;
    const float* W = (m == 0) ? Wk : ((m == 1) ? Wq : Wv);
    const int k0 = threadIdx.x * 2;
    float v0 = __ldg(W + (size_t)k0*Dn + j);
    float v1 = __ldg(W + (size_t)(k0+1)*Dn + j);
    unsigned short l0, l1;
    unsigned hi = pack_bf2(v0, v1, &l0, &l1);
    unsigned lo = (unsigned)l0 | ((unsigned)l1 << 16);
    reinterpret_cast<unsigned*>(g_Whi)[n*(Fn/2) + threadIdx.x] = hi;
    reinterpret_cast<unsigned*>(g_Wlo)[n*(Fn/2) + threadIdx.x] = lo;
}

// ---------------------------------------------------------------------------
// X-prep: LayerNorm + bf16 hi/lo split of x -> g_Xhi/g_Xlo
// 256 blocks x 256 threads; warp handles 4 rows.
// ---------------------------------------------------------------------------
__global__ void __launch_bounds__(256) xprep_kernel(
    const float* __restrict__ x,
    const float* __restrict__ gamma, const float* __restrict__ beta)
{
    const int w = threadIdx.x >> 5, l = threadIdx.x & 31;
#pragma unroll 1
    for (int rr = 0; rr < 4; rr++) {
        const int row = blockIdx.x*32 + w*4 + rr;
        const float4* xr = reinterpret_cast<const float4*>(x + (size_t)row * Fn);
        float4 v[4];
        float s = 0.f, ss = 0.f;
#pragma unroll
        for (int q = 0; q < 4; q++) {
            v[q] = xr[q*32 + l];
            s  += v[q].x + v[q].y + v[q].z + v[q].w;
            ss += v[q].x*v[q].x + v[q].y*v[q].y + v[q].z*v[q].z + v[q].w*v[q].w;
        }
#pragma unroll
        for (int o = 16; o; o >>= 1) {
            s  += __shfl_xor_sync(0xffffffffu, s,  o);
            ss += __shfl_xor_sync(0xffffffffu, ss, o);
        }
        const float mu   = s * (1.f/512.f);
        const float var  = ss * (1.f/512.f) - mu*mu;
        const float rstd = rsqrtf(var + 1e-5f);
#pragma unroll
        for (int q = 0; q < 4; q++) {
            const int c4 = q*32 + l;
            float4 g4 = __ldg(reinterpret_cast<const float4*>(gamma) + c4);
            float4 b4 = __ldg(reinterpret_cast<const float4*>(beta)  + c4);
            float vv[4] = {v[q].x, v[q].y, v[q].z, v[q].w};
            float gg[4] = {g4.x, g4.y, g4.z, g4.w};
            float bb[4] = {b4.x, b4.y, b4.z, b4.w};
#pragma unroll
            for (int e = 0; e < 4; e++) vv[e] = (vv[e] - mu)*rstd*gg[e] + bb[e];
            unsigned short s0, s1, s2, s3;
            unsigned h0 = pack_bf2(vv[0], vv[1], &s0, &s1);
            unsigned h1 = pack_bf2(vv[2], vv[3], &s2, &s3);
            unsigned lo0 = (unsigned)s0 | ((unsigned)s1 << 16);
            unsigned lo1 = (unsigned)s2 | ((unsigned)s3 << 16);
            *reinterpret_cast<uint2*>(g_Xhi + (size_t)row*Fn + c4*4) = make_uint2(h0, h1);
            *reinterpret_cast<uint2*>(g_Xlo + (size_t)row*Fn + c4*4) = make_uint2(lo0, lo1);
        }
    }
}

// ---------------------------------------------------------------------------
// GEMM: per-matrix blocks. grid (128, 3), 256 threads (8 warps: 2M x 4N).
// Warp tile 32x16. Split-bf16, 3 passes (hh, h*lo_b, lo_a*h).
// ---------------------------------------------------------------------------
__global__ void __launch_bounds__(256) gemm_kernel()
{
    extern __shared__ char smem[];
    const int tid = threadIdx.x, w = tid >> 5, l = tid & 31;
    const int mb = blockIdx.x, m = blockIdx.y;
    const int row0 = mb * MBLK;
    const unsigned sbase = smem_u32(smem);
    const int wm = w & 1, wn = w >> 1;

    unsigned a_off[2];
#pragma unroll
    for (int mt = 0; mt < 2; mt++)
        a_off[mt] = sbase + SM_AHI + (unsigned)(wm*32 + mt*16 + (l & 15))*LDAB + ((l >> 4) << 4);
    const unsigned b_off = sbase + SM_BHI
        + (unsigned)(wn*16 + ((l >> 4) << 3) + (l & 7))*LDAB + (((l >> 3) & 1) << 4);
    const unsigned ALO_D = SM_ALO - SM_AHI;
    const unsigned BLO_D = SM_BLO - SM_BHI;

    float acc[2][2][4];
#pragma unroll
    for (int mt = 0; mt < 2; mt++)
#pragma unroll
        for (int nt = 0; nt < 2; nt++)
#pragma unroll
            for (int e = 0; e < 4; e++) acc[mt][nt][e] = 0.f;

    const int sr = tid >> 2, sq = (tid & 3) * 4;   // staging: 4 threads/row, 4 uint4 each

    for (int c = 0; c < NKC; c++) {
        __syncthreads();
        // stage A (hi+lo)
        {
            const uint4* sh = reinterpret_cast<const uint4*>(g_Xhi + (size_t)(row0 + sr)*Fn) + c*16 + sq;
            const uint4* sl = reinterpret_cast<const uint4*>(g_Xlo + (size_t)(row0 + sr)*Fn) + c*16 + sq;
            uint4* dh = reinterpret_cast<uint4*>(smem + SM_AHI + sr*LDAB + sq*16);
            uint4* dl = reinterpret_cast<uint4*>(smem + SM_ALO + sr*LDAB + sq*16);
#pragma unroll
            for (int e = 0; e < 4; e++) { dh[e] = sh[e]; dl[e] = sl[e]; }
        }
        // stage B (matrix m rows)
        {
            const uint4* sh = reinterpret_cast<const uint4*>(g_Whi + (size_t)(m*64 + sr)*Fn) + c*16 + sq;
            const uint4* sl = reinterpret_cast<const uint4*>(g_Wlo + (size_t)(m*64 + sr)*Fn) + c*16 + sq;
            uint4* dh = reinterpret_cast<uint4*>(smem + SM_BHI + sr*LDAB + sq*16);
            uint4* dl = reinterpret_cast<uint4*>(smem + SM_BLO + sr*LDAB + sq*16);
#pragma unroll
            for (int e = 0; e < 4; e++) { dh[e] = sh[e]; dl[e] = sl[e]; }
        }
        __syncthreads();

#pragma unroll
        for (int ks = 0; ks < 8; ks++) {
            const unsigned koff = ks*32;
            unsigned ahi[2][4], alo[2][4], bhi[4], blo[4];
#pragma unroll
            for (int mt = 0; mt < 2; mt++) {
                LDSM4(ahi[mt], a_off[mt] + koff);
                LDSM4(alo[mt], a_off[mt] + ALO_D + koff);
            }
            LDSM4(bhi, b_off + koff);
            LDSM4(blo, b_off + BLO_D + koff);
#pragma unroll
            for (int mt = 0; mt < 2; mt++)
#pragma unroll
                for (int nt = 0; nt < 2; nt++) {
                    const int h = nt*2;
                    MMA_BF16(acc[mt][nt], ahi[mt], bhi[h], bhi[h+1]);
                    MMA_BF16(acc[mt][nt], ahi[mt], blo[h], blo[h+1]);
                    MMA_BF16(acc[mt][nt], alo[mt], bhi[h], bhi[h+1]);
                }
        }
    }

    // epilogue: stage fp32 tile (overlay A region), normalize, store
    __syncthreads();
    float* outt = reinterpret_cast<float*>(smem);   // [64][OUTS]
#pragma unroll
    for (int mt = 0; mt < 2; mt++)
#pragma unroll
        for (int nt = 0; nt < 2; nt++) {
            const int r   = wm*32 + mt*16 + (l >> 2);
            const int col = wn*16 + nt*8 + (l & 3)*2;
            *reinterpret_cast<float2*>(&outt[r*OUTS + col])     = make_float2(acc[mt][nt][0], acc[mt][nt][1]);
            *reinterpret_cast<float2*>(&outt[(r+8)*OUTS + col]) = make_float2(acc[mt][nt][2], acc[mt][nt][3]);
        }
    __syncthreads();

    float* G = (m == 0) ? g_K : ((m == 1) ? g_Q : g_V);
#pragma unroll 1
    for (int r8 = 0; r8 < 8; r8++) {
        const int r = w*8 + r8;
        const int grow = row0 + r;
        float v0 = outt[r*OUTS + l];
        float v1 = outt[r*OUTS + 32 + l];
        if (m < 2) {
            v0 = fmaxf(v0, 0.f); v1 = fmaxf(v1, 0.f);
            float s = v0 + v1;
#pragma unroll
            for (int o = 16; o; o >>= 1) s += __shfl_xor_sync(0xffffffffu, s, o);
            const float rs = 1.f / (1e-5f + s);
            v0 *= rs; v1 *= rs;
        }
        G[(size_t)grow*Dn + l]      = v0;
        G[(size_t)grow*Dn + 32 + l] = v1;
    }
}

// ---------------------------------------------------------------------------
// Kernel B: per-(batch,chunk) outer-product sums
// ---------------------------------------------------------------------------
__global__ void __launch_bounds__(256) chunk_sum_kernel()
{
    __shared__ float Kc[TC*Dn], Vc[TC*Dn];
    const int c = blockIdx.x, b = blockIdx.y;
    const int base = (b*Tn + c*TC) * Dn;
    {
        const float4* Ks = reinterpret_cast<const float4*>(g_K + base);
        const float4* Vs = reinterpret_cast<const float4*>(g_V + base);
        float4* K4 = reinterpret_cast<float4*>(Kc);
        float4* V4 = reinterpret_cast<float4*>(Vc);
        for (int i = threadIdx.x; i < TC*Dn/4; i += 256) { K4[i] = Ks[i]; V4[i] = Vs[i]; }
    }
    __syncthreads();

    const int jg = threadIdx.x & 15, ig = threadIdx.x >> 4;
    float acc[4][4] = {};
#pragma unroll 4
    for (int t = 0; t < TC; t++) {
        float4 k4 = *reinterpret_cast<const float4*>(Kc + t*Dn + jg*4);
        float4 v4 = *reinterpret_cast<const float4*>(Vc + t*Dn + ig*4);
        float kk[4] = {k4.x, k4.y, k4.z, k4.w};
        float vv[4] = {v4.x, v4.y, v4.z, v4.w};
#pragma unroll
        for (int i = 0; i < 4; i++)
#pragma unroll
            for (int j = 0; j < 4; j++) acc[i][j] += vv[i]*kk[j];
    }
    float* S = g_S + (size_t)(b*NCH + c) * (Dn*Dn);
#pragma unroll
    for (int i = 0; i < 4; i++)
        *reinterpret_cast<float4*>(S + (ig*4 + i)*Dn + jg*4) =
            make_float4(acc[i][0], acc[i][1], acc[i][2], acc[i][3]);
}

// ---------------------------------------------------------------------------
// Prefix: P[b,c] = state[b] + sum_{c'<c} S[b,c'].  grid (4, Bn), 256 thr.
// ---------------------------------------------------------------------------
__global__ void __launch_bounds__(256) prefix_kernel(const float* __restrict__ state)
{
    const int b = blockIdx.y;
    const int e = (blockIdx.x*256 + threadIdx.x) * 4;
    float4 run = __ldg(reinterpret_cast<const float4*>(state + (size_t)b*(Dn*Dn) + e));
#pragma unroll 4
    for (int c = 0; c < NCH; c++) {
        const size_t off = (size_t)(b*NCH + c)*(Dn*Dn) + e;
        *reinterpret_cast<float4*>(g_P + off) = run;
        float4 s4 = *reinterpret_cast<const float4*>(g_S + off);
        run.x += s4.x; run.y += s4.y; run.z += s4.z; run.w += s4.w;
    }
}

// ---------------------------------------------------------------------------
// Scan: grid (NCH, Bn, 2 j-halves), 256 threads.
// Thread owns rows ig*4..+3, cols jh*32 + jg*2..+1. No barrier in t-loop.
// ---------------------------------------------------------------------------
__global__ void __launch_bounds__(256) scan_kernel(float* __restrict__ out)
{
    extern __shared__ float sm[];
    float*  Kc = sm + SC_KC;               // [32][32]
    float*  Qc = sm + SC_QC;               // [32][64]
    float*  Vc = sm + SC_VC;               // [32][64]
    float2* ypbuf = reinterpret_cast<float2*>(sm + SC_YP);  // [32][8][16]

    const int c = blockIdx.x, b = blockIdx.y, jh = blockIdx.z;
    const int tid = threadIdx.x, w = tid >> 5, l = tid & 31;
    const int ig = tid >> 4, jg = tid & 15;

    // load offset state (prefix includes initial state)
    float acc[4][2];
    {
        const float* P = g_P + (size_t)(b*NCH + c)*(Dn*Dn) + jh*32 + jg*2;
#pragma unroll
        for (int i = 0; i < 4; i++) {
            float2 p2 = *reinterpret_cast<const float2*>(P + (ig*4 + i)*Dn);
            acc[i][0] = p2.x; acc[i][1] = p2.y;
        }
    }

    // stage K half, Q, V full
    {
        const int base = (b*Tn + c*TC) * Dn;
        {   // K: 32 t x 32 j-half = 256 float4
            const int t = tid >> 3, jj = (tid & 7)*4;
            *reinterpret_cast<float4*>(Kc + t*32 + jj) =
                *reinterpret_cast<const float4*>(g_K + base + t*Dn + jh*32 + jj);
        }
#pragma unroll
        for (int p = 0; p < 2; p++) {   // Q,V: 32 t x 64 = 512 float4 each
            const int idx = p*256 + tid;
            const int t = idx >> 4, jj = (idx & 15)*4;
            *reinterpret_cast<float4*>(Qc + t*Dn + jj) =
                *reinterpret_cast<const float4*>(g_Q + base + t*Dn + jj);
            *reinterpret_cast<float4*>(Vc + t*Dn + jj) =
                *reinterpret_cast<const float4*>(g_V + base + t*Dn + jj);
        }
    }
    __syncthreads();

    float* yout = out;
    float* sout = out + (size_t)ROWS * Dn;
    const int rbase0 = b*Tn + c*TC;

#pragma unroll 2
    for (int t = 0; t < TC; t++) {
        float2 k2 = *reinterpret_cast<const float2*>(Kc + t*32 + jg*2);
        float4 q4 = *reinterpret_cast<const float4*>(Qc + t*Dn + ig*4);
        float4 v4 = *reinterpret_cast<const float4*>(Vc + t*Dn + ig*4);
        float qq[4] = {q4.x, q4.y, q4.z, q4.w};
        float vv[4] = {v4.x, v4.y, v4.z, v4.w};
        float yp0 = 0.f, yp1 = 0.f;
        float* srow = sout + (size_t)(rbase0 + t)*(Dn*Dn) + jh*32 + jg*2;
#pragma unroll
        for (int i = 0; i < 4; i++) {
            acc[i][0] += vv[i]*k2.x;
            acc[i][1] += vv[i]*k2.y;
            yp0 += acc[i][0]*qq[i];
            yp1 += acc[i][1]*qq[i];
            *reinterpret_cast<float2*>(srow + (ig*4 + i)*Dn) = make_float2(acc[i][0], acc[i][1]);
        }
        yp0 += __shfl_xor_sync(0xffffffffu, yp0, 16);
        yp1 += __shfl_xor_sync(0xffffffffu, yp1, 16);
        if (l < 16) ypbuf[(t*8 + w)*16 + l] = make_float2(yp0, yp1);
    }

    __syncthreads();
    // reduce y over the 8 warps, write
#pragma unroll
    for (int s = 0; s < 2; s++) {
        const int idx = s*256 + tid;
        const int t = idx >> 4, jp = idx & 15;
        float f0 = 0.f, f1 = 0.f;
#pragma unroll
        for (int w8 = 0; w8 < 8; w8++) {
            float2 v = ypbuf[(t*8 + w8)*16 + jp];
            f0 += v.x; f1 += v.y;
        }
        *reinterpret_cast<float2*>(yout + (size_t)(rbase0 + t)*Dn + jh*32 + jp*2) =
            make_float2(f0, f1);
    }
}

// ---------------------------------------------------------------------------
extern "C" void kernel_launch(void* const* d_in, const int* in_sizes, int n_in,
                              void* d_out, int out_size)
{
    const float* x     = (const float*)d_in[0];
    const float* state = (const float*)d_in[1];
    const float* Wk    = (const float*)d_in[2];
    const float* Wq    = (const float*)d_in[3];
    const float* Wv    = (const float*)d_in[4];
    const float* gamma = (const float*)d_in[5];
    const float* beta  = (const float*)d_in[6];
    float* out = (float*)d_out;

    cudaFuncSetAttribute(gemm_kernel, cudaFuncAttributeMaxDynamicSharedMemorySize, SM_TOT);
    cudaFuncSetAttribute(scan_kernel, cudaFuncAttributeMaxDynamicSharedMemorySize, SC_TOTF*4);

    wprep_kernel<<<NTOT, 256>>>(Wk, Wq, Wv);
    xprep_kernel<<<ROWS/32, 256>>>(x, gamma, beta);
    gemm_kernel<<<dim3(ROWS/MBLK, 3), 256, SM_TOT>>>();
    chunk_sum_kernel<<<dim3(NCH, Bn), 256>>>();
    prefix_kernel<<<dim3(4, Bn), 256>>>(state);
    scan_kernel<<<dim3(NCH, Bn, 2), 256, SC_TOTF*4>>>(out);
}

// round 7
// speedup vs baseline: 1.4133x; 1.1841x over previous
#include <cuda_runtime.h>
#include <cuda_bf16.h>

// Problem constants
#define Bn 8
#define Tn 1024
#define Fn 512
#define Dn 64
#define ROWS (Bn*Tn)       // 8192
#define TC 32              // scan chunk length
#define NCH 32             // scan chunks (Tn/TC)

// GEMM tiling
#define MBLK 64            // rows per block
#define NTOT 192           // total output cols (K|Q|V)
#define KC2  64            // K chunk in bf16 elems
#define NKC2 8             // chunks
#define LDB2 144           // smem row stride bytes (64 bf16 = 128B + 16 pad)
#define OUTS 68            // epilogue fp32 tile stride

// GEMM smem: 2 stages, each {A_hi, A_lo, B_hi, B_lo} of 64 rows x 144B
#define SA_HI 0
#define SA_LO 9216
#define SB_HI 18432
#define SB_LO 27648
#define STGB  36864
#define SM_TOT (2*STGB)    // 73728

// Scratch
__device__ float g_K[ROWS*Dn];
__device__ float g_Q[ROWS*Dn];
__device__ float g_V[ROWS*Dn];
__device__ float g_S[Bn*NCH*Dn*Dn];
__device__ float g_P[Bn*NCH*Dn*Dn];         // chunk-prefix states
__device__ unsigned short g_Whi[NTOT*Fn];   // bf16 [n][k]
__device__ unsigned short g_Wlo[NTOT*Fn];
__device__ unsigned short g_Xhi[ROWS*Fn];   // LN'd x, bf16 hi
__device__ unsigned short g_Xlo[ROWS*Fn];   // bf16 lo

__device__ __forceinline__ unsigned smem_u32(const void* p){
    unsigned a;
    asm("{ .reg .u64 t; cvta.to.shared.u64 t, %1; cvt.u32.u64 %0, t; }" : "=r"(a) : "l"(p));
    return a;
}

__device__ __forceinline__ void cp16(unsigned dst, const void* src){
    asm volatile("cp.async.cg.shared.global [%0], [%1], 16;" :: "r"(dst), "l"(src));
}
#define CP_COMMIT() asm volatile("cp.async.commit_group;" ::: "memory")
#define CP_WAIT(n)  asm volatile("cp.async.wait_group %0;" :: "n"(n) : "memory")

#define LDSM4(r, addr) \
    asm volatile("ldmatrix.sync.aligned.m8n8.x4.shared.b16 {%0,%1,%2,%3}, [%4];" \
        : "=r"((r)[0]), "=r"((r)[1]), "=r"((r)[2]), "=r"((r)[3]) : "r"(addr))

#define MMA_BF16(d, a, b0, b1) \
    asm volatile("mma.sync.aligned.m16n8k16.row.col.f32.bf16.bf16.f32 " \
        "{%0,%1,%2,%3}, {%4,%5,%6,%7}, {%8,%9}, {%0,%1,%2,%3};" \
        : "+f"((d)[0]), "+f"((d)[1]), "+f"((d)[2]), "+f"((d)[3]) \
        : "r"((a)[0]), "r"((a)[1]), "r"((a)[2]), "r"((a)[3]), "r"(b0), "r"(b1))

__device__ __forceinline__ unsigned pack_bf2(float v0, float v1, unsigned short* lo0, unsigned short* lo1){
    __nv_bfloat16 h0 = __float2bfloat16(v0);
    __nv_bfloat16 h1 = __float2bfloat16(v1);
    *lo0 = __bfloat16_as_ushort(__float2bfloat16(v0 - __bfloat162float(h0)));
    *lo1 = __bfloat16_as_ushort(__float2bfloat16(v1 - __bfloat162float(h1)));
    return (unsigned)__bfloat16_as_ushort(h0) | ((unsigned)__bfloat16_as_ushort(h1) << 16);
}

// ---------------------------------------------------------------------------
// W-prep: transpose + split W into bf16 hi/lo [192][512]
// ---------------------------------------------------------------------------
__global__ void __launch_bounds__(256) wprep_kernel(
    const float* __restrict__ Wk, const float* __restrict__ Wq,
    const float* __restrict__ Wv)
{
    const int n = blockIdx.x;
    const int m = n >> 6, j = n & 63;
    const float* W = (m == 0) ? Wk : ((m == 1) ? Wq : Wv);
    const int k0 = threadIdx.x * 2;
    float v0 = __ldg(W + (size_t)k0*Dn + j);
    float v1 = __ldg(W + (size_t)(k0+1)*Dn + j);
    unsigned short l0, l1;
    unsigned hi = pack_bf2(v0, v1, &l0, &l1);
    unsigned lo = (unsigned)l0 | ((unsigned)l1 << 16);
    reinterpret_cast<unsigned*>(g_Whi)[n*(Fn/2) + threadIdx.x] = hi;
    reinterpret_cast<unsigned*>(g_Wlo)[n*(Fn/2) + threadIdx.x] = lo;
}

// ---------------------------------------------------------------------------
// X-prep: LayerNorm + bf16 hi/lo split of x -> g_Xhi/g_Xlo
// ---------------------------------------------------------------------------
__global__ void __launch_bounds__(256) xprep_kernel(
    const float* __restrict__ x,
    const float* __restrict__ gamma, const float* __restrict__ beta)
{
    const int w = threadIdx.x >> 5, l = threadIdx.x & 31;
#pragma unroll 1
    for (int rr = 0; rr < 4; rr++) {
        const int row = blockIdx.x*32 + w*4 + rr;
        const float4* xr = reinterpret_cast<const float4*>(x + (size_t)row * Fn);
        float4 v[4];
        float s = 0.f, ss = 0.f;
#pragma unroll
        for (int q = 0; q < 4; q++) {
            v[q] = xr[q*32 + l];
            s  += v[q].x + v[q].y + v[q].z + v[q].w;
            ss += v[q].x*v[q].x + v[q].y*v[q].y + v[q].z*v[q].z + v[q].w*v[q].w;
        }
#pragma unroll
        for (int o = 16; o; o >>= 1) {
            s  += __shfl_xor_sync(0xffffffffu, s,  o);
            ss += __shfl_xor_sync(0xffffffffu, ss, o);
        }
        const float mu   = s * (1.f/512.f);
        const float var  = ss * (1.f/512.f) - mu*mu;
        const float rstd = rsqrtf(var + 1e-5f);
#pragma unroll
        for (int q = 0; q < 4; q++) {
            const int c4 = q*32 + l;
            float4 g4 = __ldg(reinterpret_cast<const float4*>(gamma) + c4);
            float4 b4 = __ldg(reinterpret_cast<const float4*>(beta)  + c4);
            float vv[4] = {v[q].x, v[q].y, v[q].z, v[q].w};
            float gg[4] = {g4.x, g4.y, g4.z, g4.w};
            float bb[4] = {b4.x, b4.y, b4.z, b4.w};
#pragma unroll
            for (int e = 0; e < 4; e++) vv[e] = (vv[e] - mu)*rstd*gg[e] + bb[e];
            unsigned short s0, s1, s2, s3;
            unsigned h0 = pack_bf2(vv[0], vv[1], &s0, &s1);
            unsigned h1 = pack_bf2(vv[2], vv[3], &s2, &s3);
            unsigned lo0 = (unsigned)s0 | ((unsigned)s1 << 16);
            unsigned lo1 = (unsigned)s2 | ((unsigned)s3 << 16);
            *reinterpret_cast<uint2*>(g_Xhi + (size_t)row*Fn + c4*4) = make_uint2(h0, h1);
            *reinterpret_cast<uint2*>(g_Xlo + (size_t)row*Fn + c4*4) = make_uint2(lo0, lo1);
        }
    }
}

// ---------------------------------------------------------------------------
// GEMM: grid (128, 3), 256 threads (8 warps: 2M x 4N), cp.async 2-stage pipe.
// ---------------------------------------------------------------------------
__global__ void __launch_bounds__(256) gemm_kernel()
{
    extern __shared__ char smem[];
    const int tid = threadIdx.x, w = tid >> 5, l = tid & 31;
    const int mb = blockIdx.x, m = blockIdx.y;
    const int row0 = mb * MBLK;
    const unsigned sbase = smem_u32(smem);
    const int wm = w & 1, wn = w >> 1;

    // staging pointers: thread covers 32B (=16 bf16) of one 128B row
    const int sr = tid >> 2, seg = tid & 3;
    const char* srcAh = (const char*)(g_Xhi + (size_t)(row0 + sr)*Fn) + seg*32;
    const char* srcAl = (const char*)(g_Xlo + (size_t)(row0 + sr)*Fn) + seg*32;
    const char* srcBh = (const char*)(g_Whi + (size_t)(m*64 + sr)*Fn) + seg*32;
    const char* srcBl = (const char*)(g_Wlo + (size_t)(m*64 + sr)*Fn) + seg*32;
    const unsigned dbase = sbase + (unsigned)sr*LDB2 + seg*32;

    // ldmatrix lane addresses (within stage 0)
    unsigned a_off[2];
#pragma unroll
    for (int mt = 0; mt < 2; mt++)
        a_off[mt] = sbase + SA_HI + (unsigned)(wm*32 + mt*16 + (l & 15))*LDB2 + ((l >> 4) << 4);
    const unsigned b_off = sbase + SB_HI
        + (unsigned)(wn*16 + ((l >> 4) << 3) + (l & 7))*LDB2 + (((l >> 3) & 1) << 4);

    float acc[2][2][4];
#pragma unroll
    for (int mt = 0; mt < 2; mt++)
#pragma unroll
        for (int nt = 0; nt < 2; nt++)
#pragma unroll
            for (int e = 0; e < 4; e++) acc[mt][nt][e] = 0.f;

    // prologue: stage chunk 0
    {
        const unsigned d = dbase;
        cp16(d + SA_HI, srcAh);  cp16(d + SA_HI + 16, srcAh + 16);
        cp16(d + SA_LO, srcAl);  cp16(d + SA_LO + 16, srcAl + 16);
        cp16(d + SB_HI, srcBh);  cp16(d + SB_HI + 16, srcBh + 16);
        cp16(d + SB_LO, srcBl);  cp16(d + SB_LO + 16, srcBl + 16);
        CP_COMMIT();
    }

#pragma unroll 1
    for (int c = 0; c < NKC2; c++) {
        if (c < NKC2 - 1) {
            const unsigned d = dbase + ((c + 1) & 1)*STGB;
            const int o = (c + 1)*128;
            cp16(d + SA_HI, srcAh + o);  cp16(d + SA_HI + 16, srcAh + o + 16);
            cp16(d + SA_LO, srcAl + o);  cp16(d + SA_LO + 16, srcAl + o + 16);
            cp16(d + SB_HI, srcBh + o);  cp16(d + SB_HI + 16, srcBh + o + 16);
            cp16(d + SB_LO, srcBl + o);  cp16(d + SB_LO + 16, srcBl + o + 16);
            CP_COMMIT();
            CP_WAIT(1);
        } else {
            CP_WAIT(0);
        }
        __syncthreads();

        const unsigned so = (unsigned)(c & 1)*STGB;
#pragma unroll
        for (int ks = 0; ks < 4; ks++) {
            const unsigned koff = so + ks*32;
            unsigned ahi[2][4], alo[2][4], bhi[4], blo[4];
#pragma unroll
            for (int mt = 0; mt < 2; mt++) {
                LDSM4(ahi[mt], a_off[mt] + koff);
                LDSM4(alo[mt], a_off[mt] + koff + (SA_LO - SA_HI));
            }
            LDSM4(bhi, b_off + koff);
            LDSM4(blo, b_off + koff + (SB_LO - SB_HI));
#pragma unroll
            for (int mt = 0; mt < 2; mt++)
#pragma unroll
                for (int nt = 0; nt < 2; nt++) {
                    const int h = nt*2;
                    MMA_BF16(acc[mt][nt], ahi[mt], bhi[h], bhi[h+1]);
                    MMA_BF16(acc[mt][nt], ahi[mt], blo[h], blo[h+1]);
                    MMA_BF16(acc[mt][nt], alo[mt], bhi[h], bhi[h+1]);
                }
        }
        __syncthreads();
    }

    // epilogue: stage fp32 tile (overlay stage 0), normalize, store
    float* outt = reinterpret_cast<float*>(smem);   // [64][OUTS]
#pragma unroll
    for (int mt = 0; mt < 2; mt++)
#pragma unroll
        for (int nt = 0; nt < 2; nt++) {
            const int r   = wm*32 + mt*16 + (l >> 2);
            const int col = wn*16 + nt*8 + (l & 3)*2;
            *reinterpret_cast<float2*>(&outt[r*OUTS + col])     = make_float2(acc[mt][nt][0], acc[mt][nt][1]);
            *reinterpret_cast<float2*>(&outt[(r+8)*OUTS + col]) = make_float2(acc[mt][nt][2], acc[mt][nt][3]);
        }
    __syncthreads();

    float* G = (m == 0) ? g_K : ((m == 1) ? g_Q : g_V);
#pragma unroll 1
    for (int r8 = 0; r8 < 8; r8++) {
        const int r = w*8 + r8;
        const int grow = row0 + r;
        float v0 = outt[r*OUTS + l];
        float v1 = outt[r*OUTS + 32 + l];
        if (m < 2) {
            v0 = fmaxf(v0, 0.f); v1 = fmaxf(v1, 0.f);
            float s = v0 + v1;
#pragma unroll
            for (int o = 16; o; o >>= 1) s += __shfl_xor_sync(0xffffffffu, s, o);
            const float rs = 1.f / (1e-5f + s);
            v0 *= rs; v1 *= rs;
        }
        G[(size_t)grow*Dn + l]      = v0;
        G[(size_t)grow*Dn + 32 + l] = v1;
    }
}

// ---------------------------------------------------------------------------
// Kernel B: per-(batch,chunk) outer-product sums
// ---------------------------------------------------------------------------
__global__ void __launch_bounds__(256) chunk_sum_kernel()
{
    __shared__ float Kc[TC*Dn], Vc[TC*Dn];
    const int c = blockIdx.x, b = blockIdx.y;
    const int base = (b*Tn + c*TC) * Dn;
    {
        const float4* Ks = reinterpret_cast<const float4*>(g_K + base);
        const float4* Vs = reinterpret_cast<const float4*>(g_V + base);
        float4* K4 = reinterpret_cast<float4*>(Kc);
        float4* V4 = reinterpret_cast<float4*>(Vc);
        for (int i = threadIdx.x; i < TC*Dn/4; i += 256) { K4[i] = Ks[i]; V4[i] = Vs[i]; }
    }
    __syncthreads();

    const int jg = threadIdx.x & 15, ig = threadIdx.x >> 4;
    float acc[4][4] = {};
#pragma unroll 4
    for (int t = 0; t < TC; t++) {
        float4 k4 = *reinterpret_cast<const float4*>(Kc + t*Dn + jg*4);
        float4 v4 = *reinterpret_cast<const float4*>(Vc + t*Dn + ig*4);
        float kk[4] = {k4.x, k4.y, k4.z, k4.w};
        float vv[4] = {v4.x, v4.y, v4.z, v4.w};
#pragma unroll
        for (int i = 0; i < 4; i++)
#pragma unroll
            for (int j = 0; j < 4; j++) acc[i][j] += vv[i]*kk[j];
    }
    float* S = g_S + (size_t)(b*NCH + c) * (Dn*Dn);
#pragma unroll
    for (int i = 0; i < 4; i++)
        *reinterpret_cast<float4*>(S + (ig*4 + i)*Dn + jg*4) =
            make_float4(acc[i][0], acc[i][1], acc[i][2], acc[i][3]);
}

// ---------------------------------------------------------------------------
// Prefix: P[b,c] = state[b] + sum_{c'<c} S[b,c'].  grid (4, Bn), 256 thr.
// ---------------------------------------------------------------------------
__global__ void __launch_bounds__(256) prefix_kernel(const float* __restrict__ state)
{
    const int b = blockIdx.y;
    const int e = (blockIdx.x*256 + threadIdx.x) * 4;
    float4 run = __ldg(reinterpret_cast<const float4*>(state + (size_t)b*(Dn*Dn) + e));
#pragma unroll 4
    for (int c = 0; c < NCH; c++) {
        const size_t off = (size_t)(b*NCH + c)*(Dn*Dn) + e;
        *reinterpret_cast<float4*>(g_P + off) = run;
        float4 s4 = *reinterpret_cast<const float4*>(g_S + off);
        run.x += s4.x; run.y += s4.y; run.z += s4.z; run.w += s4.w;
    }
}

// ---------------------------------------------------------------------------
// Scan: grid (NCH, Bn, 2 j-halves), 256 threads.
// Thread owns rows ig*2..+1 (ig=tid>>3), cols jh*32 + jg*4..+3 (jg=tid&7).
// STG.128 state stores; barrier-free t-loop.
// ---------------------------------------------------------------------------
__global__ void __launch_bounds__(256) scan_kernel(float* __restrict__ out)
{
    extern __shared__ float sm[];
    float*  Kc = sm;                 // [32][32]
    float*  Qc = sm + 1024;          // [32][64]
    float*  Vc = sm + 3072;          // [32][64]
    float4* ypbuf = reinterpret_cast<float4*>(sm + 5120);  // [32 t][8 w][8 jg]

    const int c = blockIdx.x, b = blockIdx.y, jh = blockIdx.z;
    const int tid = threadIdx.x, w = tid >> 5, l = tid & 31;
    const int ig = tid >> 3, jg = tid & 7;

    float acc[2][4];
    {
        const float* P = g_P + (size_t)(b*NCH + c)*(Dn*Dn) + jh*32 + jg*4;
#pragma unroll
        for (int i = 0; i < 2; i++) {
            float4 p = *reinterpret_cast<const float4*>(P + (ig*2 + i)*Dn);
            acc[i][0] = p.x; acc[i][1] = p.y; acc[i][2] = p.z; acc[i][3] = p.w;
        }
    }

    {
        const int base = (b*Tn + c*TC) * Dn;
        {   // K half: 32 t x 32 = 256 float4
            const int t = tid >> 3, jj = (tid & 7)*4;
            *reinterpret_cast<float4*>(Kc + t*32 + jj) =
                *reinterpret_cast<const float4*>(g_K + base + t*Dn + jh*32 + jj);
        }
#pragma unroll
        for (int p = 0; p < 2; p++) {   // Q,V full: 512 float4 each
            const int idx = p*256 + tid;
            const int t = idx >> 4, jj = (idx & 15)*4;
            *reinterpret_cast<float4*>(Qc + t*Dn + jj) =
                *reinterpret_cast<const float4*>(g_Q + base + t*Dn + jj);
            *reinterpret_cast<float4*>(Vc + t*Dn + jj) =
                *reinterpret_cast<const float4*>(g_V + base + t*Dn + jj);
        }
    }
    __syncthreads();

    float* yout = out;
    float* sout = out + (size_t)ROWS * Dn;
    const int rbase0 = b*Tn + c*TC;

#pragma unroll 2
    for (int t = 0; t < TC; t++) {
        float4 k4 = *reinterpret_cast<const float4*>(Kc + t*32 + jg*4);
        float2 q2 = *reinterpret_cast<const float2*>(Qc + t*Dn + ig*2);
        float2 v2 = *reinterpret_cast<const float2*>(Vc + t*Dn + ig*2);
        const float kk[4] = {k4.x, k4.y, k4.z, k4.w};
        float yp[4] = {0.f, 0.f, 0.f, 0.f};
        float* srow = sout + (size_t)(rbase0 + t)*(Dn*Dn) + jh*32 + jg*4;

#pragma unroll
        for (int e = 0; e < 4; e++) { acc[0][e] += v2.x*kk[e]; yp[e] += acc[0][e]*q2.x; }
        *reinterpret_cast<float4*>(srow + (ig*2)*Dn) =
            make_float4(acc[0][0], acc[0][1], acc[0][2], acc[0][3]);
#pragma unroll
        for (int e = 0; e < 4; e++) { acc[1][e] += v2.y*kk[e]; yp[e] += acc[1][e]*q2.y; }
        *reinterpret_cast<float4*>(srow + (ig*2 + 1)*Dn) =
            make_float4(acc[1][0], acc[1][1], acc[1][2], acc[1][3]);

#pragma unroll
        for (int e = 0; e < 4; e++) {
            yp[e] += __shfl_xor_sync(0xffffffffu, yp[e], 8);
            yp[e] += __shfl_xor_sync(0xffffffffu, yp[e], 16);
        }
        if (l < 8) ypbuf[(t*8 + w)*8 + l] = make_float4(yp[0], yp[1], yp[2], yp[3]);
    }

    __syncthreads();
    {   // final y reduce over 8 warps: 32 t x 8 jg entries, one per thread
        const int t = tid >> 3, jp = tid & 7;
        float4 s = make_float4(0.f, 0.f, 0.f, 0.f);
#pragma unroll
        for (int w8 = 0; w8 < 8; w8++) {
            float4 v = ypbuf[(t*8 + w8)*8 + jp];
            s.x += v.x; s.y += v.y; s.z += v.z; s.w += v.w;
        }
        *reinterpret_cast<float4*>(yout + (size_t)(rbase0 + t)*Dn + jh*32 + jp*4) = s;
    }
}

// ---------------------------------------------------------------------------
extern "C" void kernel_launch(void* const* d_in, const int* in_sizes, int n_in,
                              void* d_out, int out_size)
{
    const float* x     = (const float*)d_in[0];
    const float* state = (const float*)d_in[1];
    const float* Wk    = (const float*)d_in[2];
    const float* Wq    = (const float*)d_in[3];
    const float* Wv    = (const float*)d_in[4];
    const float* gamma = (const float*)d_in[5];
    const float* beta  = (const float*)d_in[6];
    float* out = (float*)d_out;

    cudaFuncSetAttribute(gemm_kernel, cudaFuncAttributeMaxDynamicSharedMemorySize, SM_TOT);
    cudaFuncSetAttribute(scan_kernel, cudaFuncAttributeMaxDynamicSharedMemorySize, 13312*4);

    wprep_kernel<<<NTOT, 256>>>(Wk, Wq, Wv);
    xprep_kernel<<<ROWS/32, 256>>>(x, gamma, beta);
    gemm_kernel<<<dim3(ROWS/MBLK, 3), 256, SM_TOT>>>();
    chunk_sum_kernel<<<dim3(NCH, Bn), 256>>>();
    prefix_kernel<<<dim3(4, Bn), 256>>>(state);
    scan_kernel<<<dim3(NCH, Bn, 2), 256, 13312*4>>>(out);
}